// round 14
// baseline (speedup 1.0000x reference)
#include <cuda_runtime.h>
#include <cuda_fp16.h>
#include <math.h>

#define NV 786432
#define KS 5
#define EMAX (8 * NV)
#define SCAN_BLOCKS 192   // NV / 4096

// ---- static device scratch (no allocations allowed) ----
__device__ __half g_t1[(size_t)NV * 32];
__device__ __half g_t2[(size_t)NV * 32];
__device__ __half g_t3[(size_t)NV * 32];
__device__ __half g_t4[(size_t)NV * 32];
__device__ __half g_h [(size_t)NV * 32];
__device__ __half g_xh[(size_t)NV * 16];
__device__ int   g_deg[NV];          // zero at entry; finalize re-zeroes for next replay
__device__ int   g_excl[NV];
__device__ int   g_rowptr[NV + 1];
__device__ int   g_pos[NV];
__device__ int   g_bsum[SCAN_BLOCKS];
__device__ int2  g_edge[EMAX];       // (col, float_as_int(val)) interleaved

// ===========================================================================
// CSR build (4 kernels)
// ===========================================================================
__global__ void hist_kernel(const int* __restrict__ rows, int* __restrict__ deg, int nedges) {
    int e = blockIdx.x * blockDim.x + threadIdx.x;
    if (e < nedges) atomicAdd(deg + __ldg(rows + e), 1);
}

__global__ void scan_local_kernel(const int* __restrict__ deg, int* __restrict__ excl,
                                  int* __restrict__ bsum) {
    __shared__ int warp_sums[32];
    int t = threadIdx.x;
    int base = blockIdx.x * 4096 + t * 4;
    int4 d = *(const int4*)(deg + base);
    int tsum = d.x + d.y + d.z + d.w;
    int lane = t & 31, wid = t >> 5;
    int v = tsum;
#pragma unroll
    for (int o = 1; o < 32; o <<= 1) {
        int n = __shfl_up_sync(~0u, v, o);
        if (lane >= o) v += n;
    }
    if (lane == 31) warp_sums[wid] = v;
    __syncthreads();
    if (wid == 0) {
        int ws = warp_sums[lane];
#pragma unroll
        for (int o = 1; o < 32; o <<= 1) {
            int n = __shfl_up_sync(~0u, ws, o);
            if (lane >= o) ws += n;
        }
        warp_sums[lane] = ws;
    }
    __syncthreads();
    int warp_off = (wid == 0) ? 0 : warp_sums[wid - 1];
    int e0 = warp_off + v - tsum;
    excl[base + 0] = e0;
    excl[base + 1] = e0 + d.x;
    excl[base + 2] = e0 + d.x + d.y;
    excl[base + 3] = e0 + d.x + d.y + d.z;
    if (t == 0) bsum[blockIdx.x] = warp_sums[31];
}

__global__ void finalize_kernel(const int* __restrict__ excl, const int* __restrict__ bsum,
                                int* __restrict__ rowptr, int* __restrict__ pos,
                                int* __restrict__ deg, int nedges) {
    __shared__ int s[256];
    int t = threadIdx.x;
    s[t] = (t < SCAN_BLOCKS) ? bsum[t] : 0;
    __syncthreads();
#pragma unroll
    for (int o = 1; o < 256; o <<= 1) {
        int add = (t >= o) ? s[t - o] : 0;
        __syncthreads();
        s[t] += add;
        __syncthreads();
    }
    int i = blockIdx.x * 256 + t;
    if (i < NV) {
        int sb = i >> 12;
        int off = (sb == 0) ? 0 : s[sb - 1];
        int r = excl[i] + off;
        rowptr[i] = r;
        pos[i] = r;
        deg[i] = 0;
        if (i == 0) rowptr[NV] = nedges;
    }
}

__global__ void fill_kernel(const int* __restrict__ rows, const int* __restrict__ cols,
                            const float* __restrict__ vals, int* __restrict__ pos,
                            int2* __restrict__ edge, int nedges) {
    int e = blockIdx.x * blockDim.x + threadIdx.x;
    if (e >= nedges) return;
    int r = __ldg(rows + e);
    int p = atomicAdd(pos + r, 1);
    edge[p] = make_int2(__ldg(cols + e), __float_as_int(__ldg(vals + e)));
}

// x (fp32, 16 ch) -> half
__global__ void cvt_x_kernel(const float* __restrict__ x, __half* __restrict__ xh) {
    int i = blockIdx.x * blockDim.x + threadIdx.x;   // one per 8 elems
    if (i >= NV * 2) return;
    float4 a = ((const float4*)x)[i * 2];
    float4 b = ((const float4*)x)[i * 2 + 1];
    uint4 o;
    ((__half2*)&o)[0] = __floats2half2_rn(a.x, a.y);
    ((__half2*)&o)[1] = __floats2half2_rn(a.z, a.w);
    ((__half2*)&o)[2] = __floats2half2_rn(b.x, b.y);
    ((__half2*)&o)[3] = __floats2half2_rn(b.z, b.w);
    ((uint4*)xh)[i] = o;
}

// ===========================================================================
// Gather SpMM (fp16 features, fp32 accumulate) with fused recurrence:
//   t[v,:] = scale * sum_j val_j * z[col_j,:]  -  (prev ? prev[v,:] : 0)
// LPR = FIN/8 lanes per row (one uint4 = 8 half per lane).
// Edges staged into SMEM once per block (dedup). Exact 4-wide main loop +
// short scalar tail. (Unchanged from R13 best.)
// ===========================================================================
__device__ __forceinline__ void fma8(float* acc, uint4 zz, float w) {
    const __half2* hp = (const __half2*)&zz;
#pragma unroll
    for (int i = 0; i < 4; i++) {
        float2 f = __half22float2(hp[i]);
        acc[2 * i]     += w * f.x;
        acc[2 * i + 1] += w * f.y;
    }
}

template<int FIN>
__global__ void __launch_bounds__(256) spmm_kernel(
        const int* __restrict__ rowptr, const int2* __restrict__ edge,
        const __half* __restrict__ z, const __half* __restrict__ prev,
        float scale, __half* __restrict__ t) {
    constexpr int LPR = FIN / 8;
    constexpr int RPB = 256 / LPR;
    constexpr int CHUNK = 2048;            // edges staged per pass (16 KB)
    __shared__ int2 sedge[CHUNK];
    int tid = threadIdx.x;
    int v0 = blockIdx.x * RPB;
    int v  = v0 + tid / LPR;
    int f4 = tid % LPR;
    int e0 = __ldg(rowptr + v0);
    int e1 = __ldg(rowptr + v0 + RPB);
    int j0 = __ldg(rowptr + v), jend = __ldg(rowptr + v + 1);
    const uint4* z4 = (const uint4*)z + f4;
    float acc[8] = {0.f, 0.f, 0.f, 0.f, 0.f, 0.f, 0.f, 0.f};

    for (int ebase = e0; ebase < e1; ebase += CHUNK) {
        int cnt = min(CHUNK, e1 - ebase);
        if (ebase != e0) __syncthreads();
        for (int i = tid; i < cnt; i += 256)
            sedge[i] = __ldg(edge + ebase + i);    // coalesced, once per edge
        __syncthreads();

        int js = max(j0, ebase), je = min(jend, ebase + cnt);
        int j = js;
        for (; j + 4 <= je; j += 4) {              // exact 4-wide batches
            int2 e[4];
            uint4 zz[4];
#pragma unroll
            for (int u = 0; u < 4; u++) e[u] = sedge[j + u - ebase];
#pragma unroll
            for (int u = 0; u < 4; u++) zz[u] = __ldg(z4 + (size_t)e[u].x * LPR);
#pragma unroll
            for (int u = 0; u < 4; u++) fma8(acc, zz[u], __int_as_float(e[u].y));
        }
        for (; j < je; j++) {                      // <=3 scalar tail
            int2 e = sedge[j - ebase];
            uint4 zz = __ldg(z4 + (size_t)e.x * LPR);
            fma8(acc, zz, __int_as_float(e.y));
        }
    }

#pragma unroll
    for (int i = 0; i < 8; i++) acc[i] *= scale;
    if (prev) {
        uint4 pv = __ldg((const uint4*)prev + (size_t)v * LPR + f4);
        const __half2* hp = (const __half2*)&pv;
#pragma unroll
        for (int i = 0; i < 4; i++) {
            float2 f = __half22float2(hp[i]);
            acc[2 * i]     -= f.x;
            acc[2 * i + 1] -= f.y;
        }
    }
    uint4 ov;
#pragma unroll
    for (int i = 0; i < 4; i++)
        ((__half2*)&ov)[i] = __floats2half2_rn(acc[2 * i], acc[2 * i + 1]);
    ((uint4*)t)[(size_t)v * LPR + f4] = ov;
}

// ===========================================================================
// Fused 5-term GEMM + bias + ELU via packed fma.rn.f32x2 (Blackwell FFMA2:
// 2 fp32 FMAs per issue slot; ptxas never emits it from C++). W staged in
// SMEM in PAIRED layout: the (even-f, odd-f) weights for a channel sit in
// adjacent floats -> one conflict-free LDS.64 feeds one FFMA2.
// t tiles staged per-k into SMEM (coalesced); 32 fp32 acc per thread.
// OUTHALF: write __half (layer 1 -> h). Else fp32 (+ factor-4 max pool).
// ===========================================================================
template<int FIN, bool DOPOOL, bool OUTHALF>
__global__ void __launch_bounds__(256) gemm5_kernel(
        const __half* __restrict__ t0, const __half* __restrict__ t1,
        const __half* __restrict__ t2, const __half* __restrict__ t3,
        const __half* __restrict__ t4,
        const float* __restrict__ W, const float* __restrict__ bias,
        void* __restrict__ outv, float* __restrict__ pooled) {
    constexpr int QPR = FIN / 8;                 // uint4 chunks per row
    constexpr int PPK = FIN / 2;                 // feature pairs per k-term
    __shared__ float Wsh[KS * FIN * 32];         // paired: [(k*PPK+p)*64 + 2*o + (f&1)]
    __shared__ uint4 tile[256 * QPR];            // 256 rows of t_k
    __shared__ float bsh[32];
    int tid = threadIdx.x;
    for (int i = tid; i < KS * FIN * 32; i += 256) {
        int fk = i >> 5, o = i & 31;             // W row index f*KS+k, channel o
        int f = fk / KS, k = fk % KS;
        Wsh[(k * PPK + (f >> 1)) * 64 + 2 * o + (f & 1)] = W[i];
    }
    if (tid < 32) bsh[tid] = bias[tid];
    __syncthreads();

    int warp = tid >> 5, o = tid & 31;
    int vbase = blockIdx.x * 256;
    const __half* ts[KS] = {t0, t1, t2, t3, t4};

    float acc[32];
#pragma unroll
    for (int vi = 0; vi < 32; vi++) acc[vi] = bsh[o];

    for (int k = 0; k < KS; k++) {
        __syncthreads();
        const uint4* src = (const uint4*)(ts[k] + (size_t)vbase * FIN);
#pragma unroll
        for (int i = 0; i < QPR; i++)
            tile[tid + i * 256] = __ldg(src + tid + i * 256);
        __syncthreads();

        const uint4* trow = tile + (size_t)warp * 32 * QPR;
        const float* wk = Wsh + (size_t)k * PPK * 64 + 2 * o;   // pair base for channel o
        for (int vi = 0; vi < 32; vi++) {
            unsigned long long a2;
            asm("mov.b64 %0, {%1, %2};" : "=l"(a2) : "f"(0.0f), "f"(0.0f));
#pragma unroll
            for (int q = 0; q < QPR; q++) {
                uint4 tv = trow[vi * QPR + q];
                const __half2* hp = (const __half2*)&tv;
#pragma unroll
                for (int i = 0; i < 4; i++) {
                    float2 f = __half22float2(hp[i]);
                    unsigned long long ab, wp;
                    asm("mov.b64 %0, {%1, %2};" : "=l"(ab) : "f"(f.x), "f"(f.y));
                    wp = *(const unsigned long long*)(wk + (q * 4 + i) * 64);  // LDS.64 pair
                    asm("fma.rn.f32x2 %0, %1, %2, %0;" : "+l"(a2) : "l"(ab), "l"(wp));
                }
            }
            float a0, a1;
            asm("mov.b64 {%0, %1}, %2;" : "=f"(a0), "=f"(a1) : "l"(a2));
            acc[vi] += a0 + a1;
        }
    }

    float pmax = 0.0f;
    for (int vi = 0; vi < 32; vi++) {
        int v = vbase + warp * 32 + vi;
        float a = acc[vi];
        a = a > 0.0f ? a : expm1f(a);
        if (OUTHALF) {
            float an = __shfl_down_sync(~0u, a, 1);
            if (!(o & 1))
                ((__half2*)((__half*)outv + (size_t)v * 32))[o >> 1] =
                    __floats2half2_rn(a, an);
        } else {
            ((float*)outv)[(size_t)v * 32 + o] = a;
        }
        if (DOPOOL) {
            pmax = (vi & 3) ? fmaxf(pmax, a) : a;
            if ((vi & 3) == 3) pooled[(size_t)(v >> 2) * 32 + o] = pmax;
        }
    }
}

// ===========================================================================
// Host-side layer driver
// ===========================================================================
template<int FIN, bool DOPOOL, bool OUTHALF>
static void run_layer(const __half* xin, const float* W, const float* bias,
                      void* out, float* pooled,
                      __half* t1, __half* t2, __half* t3, __half* t4,
                      const int* rowptr, const int2* edge) {
    constexpr int LPR = FIN / 8;
    constexpr int RPB = 256 / LPR;
    const int spmm_blocks = NV / RPB;

    spmm_kernel<FIN><<<spmm_blocks, 256>>>(rowptr, edge, xin, nullptr, 1.0f, t1);
    spmm_kernel<FIN><<<spmm_blocks, 256>>>(rowptr, edge, t1,  xin,     2.0f, t2);
    spmm_kernel<FIN><<<spmm_blocks, 256>>>(rowptr, edge, t2,  t1,      2.0f, t3);
    spmm_kernel<FIN><<<spmm_blocks, 256>>>(rowptr, edge, t3,  t2,      2.0f, t4);

    gemm5_kernel<FIN, DOPOOL, OUTHALF><<<NV / 256, 256>>>(
        xin, t1, t2, t3, t4, W, bias, out, pooled);
}

extern "C" void kernel_launch(void* const* d_in, const int* in_sizes, int n_in,
                              void* d_out, int out_size) {
    const float* x    = (const float*)d_in[0];
    const int*   rows = (const int*)  d_in[1];
    const int*   cols = (const int*)  d_in[2];
    const float* vals = (const float*)d_in[3];
    const float* w1   = (const float*)d_in[4];
    const float* b1   = (const float*)d_in[5];
    const float* w2   = (const float*)d_in[6];
    const float* b2   = (const float*)d_in[7];
    int nedges = in_sizes[1];

    float* skip   = (float*)d_out;              // [NV, 32]
    float* pooled = skip + (size_t)NV * 32;     // [NV/4, 32]

    __half *t1, *t2, *t3, *t4, *h, *xh;
    int *deg, *excl, *rowptr, *pos, *bsum;
    int2* edge;
    cudaGetSymbolAddress((void**)&t1, g_t1);
    cudaGetSymbolAddress((void**)&t2, g_t2);
    cudaGetSymbolAddress((void**)&t3, g_t3);
    cudaGetSymbolAddress((void**)&t4, g_t4);
    cudaGetSymbolAddress((void**)&h,  g_h);
    cudaGetSymbolAddress((void**)&xh, g_xh);
    cudaGetSymbolAddress((void**)&deg,    g_deg);
    cudaGetSymbolAddress((void**)&excl,   g_excl);
    cudaGetSymbolAddress((void**)&rowptr, g_rowptr);
    cudaGetSymbolAddress((void**)&pos,    g_pos);
    cudaGetSymbolAddress((void**)&bsum,   g_bsum);
    cudaGetSymbolAddress((void**)&edge,   g_edge);

    const int TPB = 256;
    const int eblocks = (nedges + TPB - 1) / TPB;

    // ---- x -> fp16 ----
    cvt_x_kernel<<<(NV * 2 + TPB - 1) / TPB, TPB>>>(x, xh);

    // ---- CSR build (deg is zero at entry; finalize re-zeroes it) ----
    hist_kernel<<<eblocks, TPB>>>(rows, deg, nedges);
    scan_local_kernel<<<SCAN_BLOCKS, 1024>>>(deg, excl, bsum);
    finalize_kernel<<<(NV + 255) / 256, 256>>>(excl, bsum, rowptr, pos, deg, nedges);
    fill_kernel<<<eblocks, TPB>>>(rows, cols, vals, pos, edge, nedges);

    // ---- Layer 1: ChebConv(16 -> 32) + ELU -> h (fp16) ----
    run_layer<16, false, true>(xh, w1, b1, h, nullptr, t1, t2, t3, t4, rowptr, edge);

    // ---- Layer 2: ChebConv(32 -> 32) + ELU -> skip (fp32), fused pool ----
    run_layer<32, true, false>(h, w2, b2, skip, pooled, t1, t2, t3, t4, rowptr, edge);
}

// round 15
// speedup vs baseline: 1.5202x; 1.5202x over previous
#include <cuda_runtime.h>
#include <cuda_fp16.h>
#include <math.h>

#define NV 786432
#define KS 5
#define EMAX (8 * NV)
#define SCAN_BLOCKS 192   // NV / 4096

// ---- static device scratch (no allocations allowed) ----
__device__ __half g_t1[(size_t)NV * 32];
__device__ __half g_t2[(size_t)NV * 32];
__device__ __half g_t3[(size_t)NV * 32];
__device__ __half g_t4[(size_t)NV * 32];
__device__ __half g_h [(size_t)NV * 32];
__device__ __half g_xh[(size_t)NV * 16];
__device__ int      g_deg[NV];       // zero at entry; finalize re-zeroes for next replay
__device__ int      g_excl[NV];
__device__ int      g_rowptr[NV + 1];
__device__ int      g_pos[NV];
__device__ int      g_bsum[SCAN_BLOCKS];
__device__ int2     g_edge[EMAX];    // (col, float_as_int(val)) interleaved
__device__ unsigned g_w1p[KS * 1 * 256];   // fp16 B-fragment-layout weights, layer 1
__device__ unsigned g_w2p[KS * 2 * 256];   // layer 2

// ===========================================================================
// CSR build (4 kernels) — unchanged
// ===========================================================================
__global__ void hist_kernel(const int* __restrict__ rows, int* __restrict__ deg, int nedges) {
    int e = blockIdx.x * blockDim.x + threadIdx.x;
    if (e < nedges) atomicAdd(deg + __ldg(rows + e), 1);
}

__global__ void scan_local_kernel(const int* __restrict__ deg, int* __restrict__ excl,
                                  int* __restrict__ bsum) {
    __shared__ int warp_sums[32];
    int t = threadIdx.x;
    int base = blockIdx.x * 4096 + t * 4;
    int4 d = *(const int4*)(deg + base);
    int tsum = d.x + d.y + d.z + d.w;
    int lane = t & 31, wid = t >> 5;
    int v = tsum;
#pragma unroll
    for (int o = 1; o < 32; o <<= 1) {
        int n = __shfl_up_sync(~0u, v, o);
        if (lane >= o) v += n;
    }
    if (lane == 31) warp_sums[wid] = v;
    __syncthreads();
    if (wid == 0) {
        int ws = warp_sums[lane];
#pragma unroll
        for (int o = 1; o < 32; o <<= 1) {
            int n = __shfl_up_sync(~0u, ws, o);
            if (lane >= o) ws += n;
        }
        warp_sums[lane] = ws;
    }
    __syncthreads();
    int warp_off = (wid == 0) ? 0 : warp_sums[wid - 1];
    int e0 = warp_off + v - tsum;
    excl[base + 0] = e0;
    excl[base + 1] = e0 + d.x;
    excl[base + 2] = e0 + d.x + d.y;
    excl[base + 3] = e0 + d.x + d.y + d.z;
    if (t == 0) bsum[blockIdx.x] = warp_sums[31];
}

__global__ void finalize_kernel(const int* __restrict__ excl, const int* __restrict__ bsum,
                                int* __restrict__ rowptr, int* __restrict__ pos,
                                int* __restrict__ deg, int nedges) {
    __shared__ int s[256];
    int t = threadIdx.x;
    s[t] = (t < SCAN_BLOCKS) ? bsum[t] : 0;
    __syncthreads();
#pragma unroll
    for (int o = 1; o < 256; o <<= 1) {
        int add = (t >= o) ? s[t - o] : 0;
        __syncthreads();
        s[t] += add;
        __syncthreads();
    }
    int i = blockIdx.x * 256 + t;
    if (i < NV) {
        int sb = i >> 12;
        int off = (sb == 0) ? 0 : s[sb - 1];
        int r = excl[i] + off;
        rowptr[i] = r;
        pos[i] = r;
        deg[i] = 0;
        if (i == 0) rowptr[NV] = nedges;
    }
}

__global__ void fill_kernel(const int* __restrict__ rows, const int* __restrict__ cols,
                            const float* __restrict__ vals, int* __restrict__ pos,
                            int2* __restrict__ edge, int nedges) {
    int e = blockIdx.x * blockDim.x + threadIdx.x;
    if (e >= nedges) return;
    int r = __ldg(rows + e);
    int p = atomicAdd(pos + r, 1);
    edge[p] = make_int2(__ldg(cols + e), __float_as_int(__ldg(vals + e)));
}

// x (fp32, 16 ch) -> half
__global__ void cvt_x_kernel(const float* __restrict__ x, __half* __restrict__ xh) {
    int i = blockIdx.x * blockDim.x + threadIdx.x;   // one per 8 elems
    if (i >= NV * 2) return;
    float4 a = ((const float4*)x)[i * 2];
    float4 b = ((const float4*)x)[i * 2 + 1];
    uint4 o;
    ((__half2*)&o)[0] = __floats2half2_rn(a.x, a.y);
    ((__half2*)&o)[1] = __floats2half2_rn(a.z, a.w);
    ((__half2*)&o)[2] = __floats2half2_rn(b.x, b.y);
    ((__half2*)&o)[3] = __floats2half2_rn(b.z, b.w);
    ((uint4*)xh)[i] = o;
}

// W [FIN*KS, 32] fp32 -> fp16 packed in mma B-fragment order:
//   Wp[(chunk*32 + n)*8 + k2] = half2{ B[2*k2][n], B[2*k2+1][n] }
//   chunk -> buffer kb = chunk/CPB, feature base f0 = (chunk%CPB)*16
//   B[kl][n] = W[(f0+kl)*KS + kb][n]
template<int FIN>
__global__ void prep_w_kernel(const float* __restrict__ W, unsigned* __restrict__ Wp) {
    constexpr int CPB = FIN / 16;
    constexpr int NC = KS * CPB;
    int i = blockIdx.x * blockDim.x + threadIdx.x;
    if (i >= NC * 256) return;
    int c = i >> 8;
    int rem = i & 255;
    int n = rem >> 3, k2 = rem & 7;
    int kb = c / CPB, f0 = (c % CPB) * 16;
    float w0 = W[((f0 + 2 * k2) * KS + kb) * 32 + n];
    float w1 = W[((f0 + 2 * k2 + 1) * KS + kb) * 32 + n];
    __half2 h = __floats2half2_rn(w0, w1);
    Wp[i] = *(unsigned*)&h;
}

// ===========================================================================
// Gather SpMM (fp16 features, fp32 accumulate) — unchanged from R13 best.
// ===========================================================================
__device__ __forceinline__ void fma8(float* acc, uint4 zz, float w) {
    const __half2* hp = (const __half2*)&zz;
#pragma unroll
    for (int i = 0; i < 4; i++) {
        float2 f = __half22float2(hp[i]);
        acc[2 * i]     += w * f.x;
        acc[2 * i + 1] += w * f.y;
    }
}

template<int FIN>
__global__ void __launch_bounds__(256) spmm_kernel(
        const int* __restrict__ rowptr, const int2* __restrict__ edge,
        const __half* __restrict__ z, const __half* __restrict__ prev,
        float scale, __half* __restrict__ t) {
    constexpr int LPR = FIN / 8;
    constexpr int RPB = 256 / LPR;
    constexpr int CHUNK = 2048;
    __shared__ int2 sedge[CHUNK];
    int tid = threadIdx.x;
    int v0 = blockIdx.x * RPB;
    int v  = v0 + tid / LPR;
    int f4 = tid % LPR;
    int e0 = __ldg(rowptr + v0);
    int e1 = __ldg(rowptr + v0 + RPB);
    int j0 = __ldg(rowptr + v), jend = __ldg(rowptr + v + 1);
    const uint4* z4 = (const uint4*)z + f4;
    float acc[8] = {0.f, 0.f, 0.f, 0.f, 0.f, 0.f, 0.f, 0.f};

    for (int ebase = e0; ebase < e1; ebase += CHUNK) {
        int cnt = min(CHUNK, e1 - ebase);
        if (ebase != e0) __syncthreads();
        for (int i = tid; i < cnt; i += 256)
            sedge[i] = __ldg(edge + ebase + i);
        __syncthreads();

        int js = max(j0, ebase), je = min(jend, ebase + cnt);
        int j = js;
        for (; j + 4 <= je; j += 4) {
            int2 e[4];
            uint4 zz[4];
#pragma unroll
            for (int u = 0; u < 4; u++) e[u] = sedge[j + u - ebase];
#pragma unroll
            for (int u = 0; u < 4; u++) zz[u] = __ldg(z4 + (size_t)e[u].x * LPR);
#pragma unroll
            for (int u = 0; u < 4; u++) fma8(acc, zz[u], __int_as_float(e[u].y));
        }
        for (; j < je; j++) {
            int2 e = sedge[j - ebase];
            uint4 zz = __ldg(z4 + (size_t)e.x * LPR);
            fma8(acc, zz, __int_as_float(e.y));
        }
    }

#pragma unroll
    for (int i = 0; i < 8; i++) acc[i] *= scale;
    if (prev) {
        uint4 pv = __ldg((const uint4*)prev + (size_t)v * LPR + f4);
        const __half2* hp = (const __half2*)&pv;
#pragma unroll
        for (int i = 0; i < 4; i++) {
            float2 f = __half22float2(hp[i]);
            acc[2 * i]     -= f.x;
            acc[2 * i + 1] -= f.y;
        }
    }
    uint4 ov;
#pragma unroll
    for (int i = 0; i < 4; i++)
        ((__half2*)&ov)[i] = __floats2half2_rn(acc[2 * i], acc[2 * i + 1]);
    ((uint4*)t)[(size_t)v * LPR + f4] = ov;
}

// ===========================================================================
// HMMA gemm5: out[256v, 32] = ELU( [t0..t4] @ W + b ) via mma.sync.m16n8k16.
// Per warp: 32 vertices (2 m-tiles) x 32 channels (4 n-tiles) x KS*FIN K.
// A fragments from padded SMEM tile (staged per buffer, coalesced);
// B fragments from pre-packed fp16 Wp (copied to SMEM once).
// Epilogue: ELU in-fragment; DOPOOL: shfl_xor max over 4-row groups;
// OUTHALF packs half2.
// ===========================================================================
__device__ __forceinline__ float eluf(float a) { return a > 0.0f ? a : expm1f(a); }

template<int FIN, bool DOPOOL, bool OUTHALF>
__global__ void __launch_bounds__(256) gemm5_kernel(
        const __half* __restrict__ t0, const __half* __restrict__ t1,
        const __half* __restrict__ t2, const __half* __restrict__ t3,
        const __half* __restrict__ t4,
        const unsigned* __restrict__ Wp, const float* __restrict__ bias,
        void* __restrict__ outv, float* __restrict__ pooled) {
    constexpr int CPB = FIN / 16;               // k16 chunks per buffer
    constexpr int WPR = FIN / 2;                // uint words per t row
    constexpr int PADW = WPR + 2;               // padded row stride (words)
    __shared__ unsigned Wsh[KS * CPB * 256];
    __shared__ unsigned tile[256 * PADW];
    __shared__ float bsh[32];
    int tid = threadIdx.x;
    for (int i = tid; i < KS * CPB * 256; i += 256) Wsh[i] = Wp[i];
    if (tid < 32) bsh[tid] = bias[tid];

    int lane = tid & 31, w = tid >> 5;
    int g = lane >> 2, c = lane & 3;            // g = row/col group, c = pair idx
    int vbase = blockIdx.x * 256;

    float acc[2][4][4];
#pragma unroll
    for (int m = 0; m < 2; m++)
#pragma unroll
        for (int j = 0; j < 4; j++) {
            // first sync below also covers bsh; but read after __syncthreads to be safe
            acc[m][j][0] = acc[m][j][1] = acc[m][j][2] = acc[m][j][3] = 0.0f;
        }

    const __half* ts[KS] = {t0, t1, t2, t3, t4};
    int chunk = 0;
    for (int kb = 0; kb < KS; kb++) {
        __syncthreads();                         // also publishes Wsh/bsh on kb==0
        const unsigned* src = (const unsigned*)(ts[kb] + (size_t)vbase * FIN);
#pragma unroll
        for (int i = 0; i < WPR; i++) {
            int idx = tid + i * 256;
            int row = idx / WPR, cw = idx % WPR;
            tile[row * PADW + cw] = __ldg(src + idx);
        }
        __syncthreads();

#pragma unroll
        for (int cc = 0; cc < CPB; cc++, chunk++) {
            unsigned b0[4], b1[4];
            const unsigned* wb = Wsh + chunk * 256;
#pragma unroll
            for (int j = 0; j < 4; j++) {
                b0[j] = wb[(j * 8 + g) * 8 + c];
                b1[j] = wb[(j * 8 + g) * 8 + c + 4];
            }
#pragma unroll
            for (int m = 0; m < 2; m++) {
                const unsigned* tb = tile + (w * 32 + m * 16) * PADW + cc * 8;
                unsigned a0 = tb[g * PADW + c];
                unsigned a1 = tb[(g + 8) * PADW + c];
                unsigned a2 = tb[g * PADW + c + 4];
                unsigned a3 = tb[(g + 8) * PADW + c + 4];
#pragma unroll
                for (int j = 0; j < 4; j++) {
                    asm volatile(
                        "mma.sync.aligned.m16n8k16.row.col.f32.f16.f16.f32 "
                        "{%0,%1,%2,%3}, {%4,%5,%6,%7}, {%8,%9}, {%0,%1,%2,%3};"
                        : "+f"(acc[m][j][0]), "+f"(acc[m][j][1]),
                          "+f"(acc[m][j][2]), "+f"(acc[m][j][3])
                        : "r"(a0), "r"(a1), "r"(a2), "r"(a3), "r"(b0[j]), "r"(b1[j]));
                }
            }
        }
    }

    // epilogue: bias + ELU + store (+pool)
#pragma unroll
    for (int m = 0; m < 2; m++) {
        int mrow = vbase + w * 32 + m * 16;
#pragma unroll
        for (int j = 0; j < 4; j++) {
            int col = j * 8 + 2 * c;
            float bb0 = bsh[col], bb1 = bsh[col + 1];
            float e0 = eluf(acc[m][j][0] + bb0), e1 = eluf(acc[m][j][1] + bb1);
            float e2 = eluf(acc[m][j][2] + bb0), e3 = eluf(acc[m][j][3] + bb1);
            if (OUTHALF) {
                ((__half2*)((__half*)outv + (size_t)(mrow + g) * 32))[col >> 1] =
                    __floats2half2_rn(e0, e1);
                ((__half2*)((__half*)outv + (size_t)(mrow + g + 8) * 32))[col >> 1] =
                    __floats2half2_rn(e2, e3);
            } else {
                *(float2*)((float*)outv + (size_t)(mrow + g) * 32 + col) =
                    make_float2(e0, e1);
                *(float2*)((float*)outv + (size_t)(mrow + g + 8) * 32 + col) =
                    make_float2(e2, e3);
            }
            if (DOPOOL) {
                float p0 = e0, p1 = e1, q0 = e2, q1 = e3;
#pragma unroll
                for (int s = 4; s <= 8; s <<= 1) {
                    p0 = fmaxf(p0, __shfl_xor_sync(~0u, p0, s));
                    p1 = fmaxf(p1, __shfl_xor_sync(~0u, p1, s));
                    q0 = fmaxf(q0, __shfl_xor_sync(~0u, q0, s));
                    q1 = fmaxf(q1, __shfl_xor_sync(~0u, q1, s));
                }
                if (g == 0 || g == 4) {
                    int pb = (mrow >> 2) + (g >> 2);       // pools for rows mrow..mrow+7
                    *(float2*)(pooled + (size_t)pb * 32 + col) = make_float2(p0, p1);
                    *(float2*)(pooled + (size_t)(pb + 2) * 32 + col) = make_float2(q0, q1);
                }
            }
        }
    }
}

// ===========================================================================
// Host-side layer driver
// ===========================================================================
template<int FIN, bool DOPOOL, bool OUTHALF>
static void run_layer(const __half* xin, const unsigned* Wp, const float* bias,
                      void* out, float* pooled,
                      __half* t1, __half* t2, __half* t3, __half* t4,
                      const int* rowptr, const int2* edge) {
    constexpr int LPR = FIN / 8;
    constexpr int RPB = 256 / LPR;
    const int spmm_blocks = NV / RPB;

    spmm_kernel<FIN><<<spmm_blocks, 256>>>(rowptr, edge, xin, nullptr, 1.0f, t1);
    spmm_kernel<FIN><<<spmm_blocks, 256>>>(rowptr, edge, t1,  xin,     2.0f, t2);
    spmm_kernel<FIN><<<spmm_blocks, 256>>>(rowptr, edge, t2,  t1,      2.0f, t3);
    spmm_kernel<FIN><<<spmm_blocks, 256>>>(rowptr, edge, t3,  t2,      2.0f, t4);

    gemm5_kernel<FIN, DOPOOL, OUTHALF><<<NV / 256, 256>>>(
        xin, t1, t2, t3, t4, Wp, bias, out, pooled);
}

extern "C" void kernel_launch(void* const* d_in, const int* in_sizes, int n_in,
                              void* d_out, int out_size) {
    const float* x    = (const float*)d_in[0];
    const int*   rows = (const int*)  d_in[1];
    const int*   cols = (const int*)  d_in[2];
    const float* vals = (const float*)d_in[3];
    const float* w1   = (const float*)d_in[4];
    const float* b1   = (const float*)d_in[5];
    const float* w2   = (const float*)d_in[6];
    const float* b2   = (const float*)d_in[7];
    int nedges = in_sizes[1];

    float* skip   = (float*)d_out;              // [NV, 32]
    float* pooled = skip + (size_t)NV * 32;     // [NV/4, 32]

    __half *t1, *t2, *t3, *t4, *h, *xh;
    int *deg, *excl, *rowptr, *pos, *bsum;
    int2* edge;
    unsigned *w1p, *w2p;
    cudaGetSymbolAddress((void**)&t1, g_t1);
    cudaGetSymbolAddress((void**)&t2, g_t2);
    cudaGetSymbolAddress((void**)&t3, g_t3);
    cudaGetSymbolAddress((void**)&t4, g_t4);
    cudaGetSymbolAddress((void**)&h,  g_h);
    cudaGetSymbolAddress((void**)&xh, g_xh);
    cudaGetSymbolAddress((void**)&deg,    g_deg);
    cudaGetSymbolAddress((void**)&excl,   g_excl);
    cudaGetSymbolAddress((void**)&rowptr, g_rowptr);
    cudaGetSymbolAddress((void**)&pos,    g_pos);
    cudaGetSymbolAddress((void**)&bsum,   g_bsum);
    cudaGetSymbolAddress((void**)&edge,   g_edge);
    cudaGetSymbolAddress((void**)&w1p,    g_w1p);
    cudaGetSymbolAddress((void**)&w2p,    g_w2p);

    const int TPB = 256;
    const int eblocks = (nedges + TPB - 1) / TPB;

    // ---- x -> fp16; W -> fp16 fragment layout ----
    cvt_x_kernel<<<(NV * 2 + TPB - 1) / TPB, TPB>>>(x, xh);
    prep_w_kernel<16><<<(KS * 1 * 256 + TPB - 1) / TPB, TPB>>>(w1, w1p);
    prep_w_kernel<32><<<(KS * 2 * 256 + TPB - 1) / TPB, TPB>>>(w2, w2p);

    // ---- CSR build (deg is zero at entry; finalize re-zeroes it) ----
    hist_kernel<<<eblocks, TPB>>>(rows, deg, nedges);
    scan_local_kernel<<<SCAN_BLOCKS, 1024>>>(deg, excl, bsum);
    finalize_kernel<<<(NV + 255) / 256, 256>>>(excl, bsum, rowptr, pos, deg, nedges);
    fill_kernel<<<eblocks, TPB>>>(rows, cols, vals, pos, edge, nedges);

    // ---- Layer 1: ChebConv(16 -> 32) + ELU -> h (fp16) ----
    run_layer<16, false, true>(xh, w1p, b1, h, nullptr, t1, t2, t3, t4, rowptr, edge);

    // ---- Layer 2: ChebConv(32 -> 32) + ELU -> skip (fp32), fused pool ----
    run_layer<32, true, false>(h, w2p, b2, skip, pooled, t1, t2, t3, t4, rowptr, edge);
}